// round 4
// baseline (speedup 1.0000x reference)
#include <cuda_runtime.h>
#include <math.h>

// ---------------- problem constants ----------------
#define NTOT  12288          // H*W*3
#define BATCH 64
#define KC    4096           // K per k-split chunk
#define NKC   3              // number of k-splits (3*4096 = 12288)
#define JT    128            // output columns per block
#define KB    32             // k per smem stage
#define OW    66             // obs smem row stride (pad: 2-way max bank conflict, 8B aligned)

// k-split partial results: [NKC][BATCH][NTOT]  (~9.4 MB static scratch)
__device__ __align__(16) float g_part[NKC * BATCH * NTOT];

#define FMA2(acc, a, b) \
    asm("fma.rn.f32x2 %0, %1, %2, %0;" : "+l"(acc) : "l"(a), "l"(b))

// ================= Kernel A: phi partial GEMM =================
// out-tile 64(M) x 128(N) per block, k-chunk 4096, FFMA2 (2 rows packed per 64-bit lane)
__global__ __launch_bounds__(256, 2)
void gemm_kernel(const float* __restrict__ obs, const float* __restrict__ w)
{
    extern __shared__ float sm[];
    float* sW = sm;                 // [2][KB][JT]
    float* sO = sm + 2 * KB * JT;   // [2][KB][OW] (rows 0..63 used)

    const int tid = threadIdx.x;
    const int j0  = blockIdx.x * JT;
    const int k0  = blockIdx.y * KC;

    // loader mapping
    const int kkL  = tid >> 5;   // 0..7 : w row within stage (stride 8)
    const int jjL  = tid & 31;   // w column-group (float4)
    const int kkO  = tid & 31;   // obs k within stage
    const int rowO = tid >> 5;   // obs row base (stride 8)

    // compute mapping
    const int rg = tid >> 5;     // row group: rows 8*rg .. 8*rg+7 (4 packed pairs)
    const int jj = tid & 31;     // column group: cols j0+4*jj .. +3

    const float* wbase = w   + (size_t)k0 * NTOT + j0 + jjL * 4;
    const float* obase = obs + (size_t)rowO * NTOT + k0 + kkO;

    float4 wr[4];
    float  orr[8];

    // prefetch stage 0
    {
        const float* wp = wbase + (size_t)kkL * NTOT;
        #pragma unroll
        for (int i = 0; i < 4; ++i)
            wr[i] = *(const float4*)(wp + (size_t)(8 * i) * NTOT);
        #pragma unroll
        for (int r = 0; r < 8; ++r)
            orr[r] = obase[(size_t)(8 * r) * NTOT];
    }

    unsigned long long acc[4][4];
    #pragma unroll
    for (int m = 0; m < 4; ++m)
        #pragma unroll
        for (int c = 0; c < 4; ++c) acc[m][c] = 0ULL;

    const int NIT = KC / KB;   // 128 stages
    for (int it = 0; it < NIT; ++it) {
        const int buf = it & 1;
        float* sWb = sW + buf * (KB * JT);
        float* sOb = sO + buf * (KB * OW);

        // commit prefetched stage to smem
        #pragma unroll
        for (int i = 0; i < 4; ++i)
            *(float4*)(sWb + (kkL + 8 * i) * JT + jjL * 4) = wr[i];
        #pragma unroll
        for (int r = 0; r < 8; ++r)
            sOb[kkO * OW + rowO + 8 * r] = orr[r];

        // prefetch next stage (latency overlapped with compute below)
        if (it + 1 < NIT) {
            const float* wp = wbase + (size_t)((it + 1) * KB + kkL) * NTOT;
            #pragma unroll
            for (int i = 0; i < 4; ++i)
                wr[i] = *(const float4*)(wp + (size_t)(8 * i) * NTOT);
            const float* op = obase + (it + 1) * KB;
            #pragma unroll
            for (int r = 0; r < 8; ++r)
                orr[r] = op[(size_t)(8 * r) * NTOT];
        }

        __syncthreads();   // one barrier per stage (ping-pong buffers)

        #pragma unroll
        for (int kk = 0; kk < KB; ++kk) {
            const float4 wv = *(const float4*)(sWb + kk * JT + jj * 4);
            unsigned long long wd0, wd1, wd2, wd3;
            asm("mov.b64 %0, {%1, %1};" : "=l"(wd0) : "f"(wv.x));
            asm("mov.b64 %0, {%1, %1};" : "=l"(wd1) : "f"(wv.y));
            asm("mov.b64 %0, {%1, %1};" : "=l"(wd2) : "f"(wv.z));
            asm("mov.b64 %0, {%1, %1};" : "=l"(wd3) : "f"(wv.w));
            const float* ob = sOb + kk * OW + 8 * rg;   // broadcast within warp
            unsigned long long a0 = *(const unsigned long long*)(ob + 0);
            unsigned long long a1 = *(const unsigned long long*)(ob + 2);
            unsigned long long a2 = *(const unsigned long long*)(ob + 4);
            unsigned long long a3 = *(const unsigned long long*)(ob + 6);
            FMA2(acc[0][0], a0, wd0); FMA2(acc[0][1], a0, wd1);
            FMA2(acc[0][2], a0, wd2); FMA2(acc[0][3], a0, wd3);
            FMA2(acc[1][0], a1, wd0); FMA2(acc[1][1], a1, wd1);
            FMA2(acc[1][2], a1, wd2); FMA2(acc[1][3], a1, wd3);
            FMA2(acc[2][0], a2, wd0); FMA2(acc[2][1], a2, wd1);
            FMA2(acc[2][2], a2, wd2); FMA2(acc[2][3], a2, wd3);
            FMA2(acc[3][0], a3, wd0); FMA2(acc[3][1], a3, wd1);
            FMA2(acc[3][2], a3, wd2); FMA2(acc[3][3], a3, wd3);
        }
    }

    // write partials
    float* outp = g_part + (size_t)blockIdx.y * (BATCH * NTOT);
    #pragma unroll
    for (int m = 0; m < 4; ++m) {
        float lo[4], hi[4];
        #pragma unroll
        for (int c = 0; c < 4; ++c)
            asm("mov.b64 {%0, %1}, %2;" : "=f"(lo[c]), "=f"(hi[c]) : "l"(acc[m][c]));
        const int row = 8 * rg + 2 * m;
        float4 v0 = make_float4(lo[0], lo[1], lo[2], lo[3]);
        float4 v1 = make_float4(hi[0], hi[1], hi[2], hi[3]);
        *(float4*)(outp + (size_t)row       * NTOT + j0 + jj * 4) = v0;
        *(float4*)(outp + (size_t)(row + 1) * NTOT + j0 + jj * 4) = v1;
    }
}

// ================= Kernel B: combine + softmax + VIN + head =================
// One block per batch element. 512 threads.
// shared layout (floats):
//   sC[4*4096] | sP[4096] | sRin[4096] | sRout[4096] | sVa[4356] | sVb[4356]
//   | sRed[16] | sPatch[36] | sH[16] | sIdx(20 ints)
#define OFF_C     0
#define OFF_P     16384
#define OFF_RIN   20480
#define OFF_ROUT  24576
#define OFF_VA    28672
#define OFF_VB    33028
#define OFF_RED   37384
#define OFF_PATCH 37400
#define OFF_H     37436
#define OFF_IDX   37452
#define SMEMB_FLOATS 37472

__global__ __launch_bounds__(512, 1)
void vin_kernel(const float* __restrict__ obs,
                const float* __restrict__ bias,
                const float* __restrict__ w1, const float* __restrict__ b1,
                const float* __restrict__ w2, const float* __restrict__ b2,
                float* __restrict__ out)
{
    extern __shared__ float sm[];
    float* sC    = sm + OFF_C;
    float* sP    = sm + OFF_P;
    float* sRin  = sm + OFF_RIN;
    float* sRout = sm + OFF_ROUT;
    float* sVa   = sm + OFF_VA;
    float* sVb   = sm + OFF_VB;
    float* sRed  = sm + OFF_RED;
    float* sPatch= sm + OFF_PATCH;
    float* sH    = sm + OFF_H;
    int*   sIdx  = (int*)(sm + OFF_IDX);

    const int b    = blockIdx.x;
    const int tid  = threadIdx.x;
    const int lane = tid & 31;
    const int wid  = tid >> 5;

    const float* pA = g_part + (size_t)(0 * BATCH + b) * NTOT;
    const float* pB = g_part + (size_t)(1 * BATCH + b) * NTOT;
    const float* pC = g_part + (size_t)(2 * BATCH + b) * NTOT;

    // ---- combine partials + bias, split into channels ----
    for (int cell = tid; cell < 4096; cell += 512) {
        int j = cell * 3;
        sRin[cell]  = pA[j]     + pB[j]     + pC[j]     + bias[j];
        sRout[cell] = pA[j + 1] + pB[j + 1] + pC[j + 1] + bias[j + 1];
        sP[cell]    = pA[j + 2] + pB[j + 2] + pC[j + 2] + bias[j + 2];
    }
    for (int i = tid; i < 4356; i += 512) { sVa[i] = 0.f; sVb[i] = 0.f; }
    __syncthreads();

    // ---- softmax over sP (4096) ----
    float m = -INFINITY;
    #pragma unroll
    for (int r = 0; r < 8; ++r) m = fmaxf(m, sP[tid + 512 * r]);
    #pragma unroll
    for (int off = 16; off; off >>= 1)
        m = fmaxf(m, __shfl_xor_sync(0xffffffffu, m, off));
    if (lane == 0) sRed[wid] = m;
    __syncthreads();
    float gm = sRed[0];
    #pragma unroll
    for (int i = 1; i < 16; ++i) gm = fmaxf(gm, sRed[i]);
    __syncthreads();            // protect sRed before reuse
    float s = 0.f;
    #pragma unroll
    for (int r = 0; r < 8; ++r) {
        int c = tid + 512 * r;
        float e = expf(sP[c] - gm);
        sP[c] = e; s += e;
    }
    #pragma unroll
    for (int off = 16; off; off >>= 1)
        s += __shfl_xor_sync(0xffffffffu, s, off);
    if (lane == 0) sRed[wid] = s;
    __syncthreads();
    float tot = 0.f;
    #pragma unroll
    for (int i = 0; i < 16; ++i) tot += sRed[i];
    float inv = 1.0f / tot;
    #pragma unroll
    for (int r = 0; r < 8; ++r) sP[tid + 512 * r] *= inv;

    // ---- per-direction constants: c = rin_sh - rout * (rin_sh != 0) ----
    for (int cell = tid; cell < 4096; cell += 512) {
        int h = cell >> 6, w_ = cell & 63;
        float rc = sRout[cell];
        float cu = 0.f, cd = 0.f, cl = 0.f, cr = 0.f;
        if (h > 0)   { float rn = sRin[cell - 64]; cu = rn - (rn != 0.f ? rc : 0.f); }
        if (h < 63)  { float rn = sRin[cell + 64]; cd = rn - (rn != 0.f ? rc : 0.f); }
        if (w_ > 0)  { float rn = sRin[cell - 1];  cl = rn - (rn != 0.f ? rc : 0.f); }
        if (w_ < 63) { float rn = sRin[cell + 1];  cr = rn - (rn != 0.f ? rc : 0.f); }
        sC[cell] = cu; sC[4096 + cell] = cd; sC[8192 + cell] = cl; sC[12288 + cell] = cr;
    }
    __syncthreads();   // sP normalization + sC complete

    // ---- K=64 value-iteration sweeps on padded 66x66 ping-pong V ----
    float pr[8], c0[8], c1[8], c2[8], c3[8];
    int   px[8];
    #pragma unroll
    for (int r = 0; r < 8; ++r) {
        int cell = tid + 512 * r;
        int h = cell >> 6, w_ = cell & 63;
        px[r] = (h + 1) * 66 + (w_ + 1);
        pr[r] = sP[cell];
        c0[r] = sC[cell];          c1[r] = sC[4096 + cell];
        c2[r] = sC[8192 + cell];   c3[r] = sC[12288 + cell];
    }
    float* cur = sVa;
    float* nxt = sVb;
    for (int itv = 0; itv < 64; ++itv) {
        #pragma unroll
        for (int r = 0; r < 8; ++r) {
            int pi = px[r];
            float nv = fmaf(pr[r], cur[pi - 66], c0[r]);            // up
            nv = fmaxf(nv, fmaf(pr[r], cur[pi + 66], c1[r]));       // down
            nv = fmaxf(nv, fmaf(pr[r], cur[pi - 1],  c2[r]));       // left
            nv = fmaxf(nv, fmaf(pr[r], cur[pi + 1],  c3[r]));       // right
            nxt[pi] = fmaxf(cur[pi], nv);
        }
        __syncthreads();
        float* t = cur; cur = nxt; nxt = t;
    }
    // final V is in `cur` (64 swaps -> sVa)

    // ---- argmax of obs channel 1 (first-max semantics) ----
    const float* ob = obs + (size_t)b * NTOT;
    float bv = -INFINITY; int bi = 0;
    #pragma unroll
    for (int r = 0; r < 8; ++r) {
        int cell = tid + 512 * r;
        float v = ob[cell * 3 + 1];
        if (v > bv) { bv = v; bi = cell; }
    }
    #pragma unroll
    for (int off = 16; off; off >>= 1) {
        float ov = __shfl_down_sync(0xffffffffu, bv, off);
        int   oi = __shfl_down_sync(0xffffffffu, bi, off);
        if (ov > bv || (ov == bv && oi < bi)) { bv = ov; bi = oi; }
    }
    if (lane == 0) { sRed[wid] = bv; sIdx[wid] = bi; }
    __syncthreads();
    if (tid == 0) {
        float bb = sRed[0]; int ii = sIdx[0];
        for (int i = 1; i < 16; ++i)
            if (sRed[i] > bb || (sRed[i] == bb && sIdx[i] < ii)) { bb = sRed[i]; ii = sIdx[i]; }
        sIdx[16] = ii;
    }
    __syncthreads();
    const int am  = sIdx[16];
    const int pi_ = am >> 6, pj_ = am & 63;

    // ---- 3x3x4 patch around agent, channels 0-2 from obs, 3 from V ----
    if (tid < 36) {
        int di = tid / 12, rem = tid % 12;
        int dj = rem >> 2, ch = rem & 3;
        float v;
        if (ch == 3) {
            v = cur[(pi_ + di) * 66 + (pj_ + dj)];   // padded V
        } else {
            int hh = pi_ + di - 1, ww = pj_ + dj - 1;
            v = (hh >= 0 && hh < 64 && ww >= 0 && ww < 64)
                    ? ob[(hh * 64 + ww) * 3 + ch] : 0.f;
        }
        sPatch[tid] = v;
    }
    __syncthreads();
    if (tid < 16) {
        float a = b1[tid];
        #pragma unroll
        for (int i = 0; i < 36; ++i) a = fmaf(sPatch[i], w1[i * 16 + tid], a);
        sH[tid] = fmaxf(a, 0.f);
    }
    __syncthreads();
    if (tid < 4) {
        float a = b2[tid];
        #pragma unroll
        for (int o = 0; o < 16; ++o) a = fmaf(sH[o], w2[o * 4 + tid], a);
        out[b * 4 + tid] = a;
    }
}

// ================= launcher =================
extern "C" void kernel_launch(void* const* d_in, const int* in_sizes, int n_in,
                              void* d_out, int out_size)
{
    const float* obs  = (const float*)d_in[0];
    const float* phiw = (const float*)d_in[1];
    const float* phib = (const float*)d_in[2];
    const float* w1   = (const float*)d_in[3];
    const float* b1   = (const float*)d_in[4];
    const float* w2   = (const float*)d_in[5];
    const float* b2   = (const float*)d_in[6];
    float* out = (float*)d_out;

    const int smemA = (2 * KB * JT + 2 * KB * OW) * (int)sizeof(float);   // 49664 B
    const int smemB = SMEMB_FLOATS * (int)sizeof(float);                  // 149888 B

    cudaFuncSetAttribute(gemm_kernel, cudaFuncAttributeMaxDynamicSharedMemorySize, smemA);
    cudaFuncSetAttribute(vin_kernel,  cudaFuncAttributeMaxDynamicSharedMemorySize, smemB);

    gemm_kernel<<<dim3(96, NKC), 256, smemA>>>(obs, phiw);
    vin_kernel<<<BATCH, 512, smemB>>>(obs, phib, w1, b1, w2, b2, out);
}